// round 1
// baseline (speedup 1.0000x reference)
#include <cuda_runtime.h>
#include <cuda_bf16.h>
#include <math.h>

// Problem dims (fixed by the reference)
#define BATCH 8
#define HW    4096     // 64*64 query positions
#define LCTX  1024     // 32*32 context positions
#define EMB   512

// ---------------- scratch (device globals; no allocs allowed) ----------------
__device__ float g_Wq[EMB * EMB];                       // folded proj_in^T @ wq
__device__ float g_bq[EMB];                             // folded bias
__device__ float g_Q [(long)BATCH * HW   * EMB];        // 64 MB
__device__ float g_K [(long)BATCH * LCTX * EMB];        // 16 MB
__device__ float g_V [(long)BATCH * LCTX * EMB];        // 16 MB
__device__ float g_S [(long)BATCH * HW   * LCTX];       // 128 MB attention logits/probs
__device__ float g_Z [(long)BATCH * (EMB + EMB) * HW];  // 128 MB concat buffer [b][1024][4096]

// ---------------- generic tiled SGEMM ----------------
// C[m,n] = alpha * sum_k A(k,m)*B(k,n) + biasM[m] + biasN[n]
//   AT=true : A stored [K,M]  -> A[k*lda+m]
//   AT=false: A stored [M,K]  -> A[m*lda+k]
//   BT=false: B stored [K,N]  -> B[k*ldb+n]
//   BT=true : B stored [N,K]  -> B[n*ldb+k]
// Requires M%128==0, N%128==0, K%16==0. blockIdx.z = batch.
#define BM 128
#define BN 128
#define BKD 16
#define TM 8
#define TN 8

template<bool AT, bool BT>
__global__ void __launch_bounds__(256)
sgemm_kernel(const float* __restrict__ A, int lda, long strideA,
             const float* __restrict__ B, int ldb, long strideB,
             float* __restrict__ C, int ldc, long strideC,
             int M, int N, int K, float alpha,
             const float* __restrict__ biasM, const float* __restrict__ biasN)
{
    __shared__ float As[BKD][BM + 4];
    __shared__ float Bs[BKD][BN + 4];

    const int bz = blockIdx.z;
    A += (long)bz * strideA;
    B += (long)bz * strideB;
    C += (long)bz * strideC;

    const int m0 = blockIdx.y * BM;
    const int n0 = blockIdx.x * BN;
    const int tid = threadIdx.x;
    const int tx = tid % (BN / TN);   // 0..15 (n)
    const int ty = tid / (BN / TN);   // 0..15 (m)

    float acc[TM][TN];
#pragma unroll
    for (int i = 0; i < TM; i++)
#pragma unroll
        for (int j = 0; j < TN; j++) acc[i][j] = 0.f;

    for (int k0 = 0; k0 < K; k0 += BKD) {
        // ---- stage A tile ----
        if (AT) {
#pragma unroll
            for (int t = 0; t < (BKD * BM) / 256; t++) {
                int i = tid + t * 256;
                int k = i / BM, m = i % BM;
                As[k][m] = A[(long)(k0 + k) * lda + (m0 + m)];
            }
        } else {
#pragma unroll
            for (int t = 0; t < (BKD * BM) / 256; t++) {
                int i = tid + t * 256;
                int m = i / BKD, k = i % BKD;
                As[k][m] = A[(long)(m0 + m) * lda + (k0 + k)];
            }
        }
        // ---- stage B tile ----
        if (!BT) {
#pragma unroll
            for (int t = 0; t < (BKD * BN) / 256; t++) {
                int i = tid + t * 256;
                int k = i / BN, n = i % BN;
                Bs[k][n] = B[(long)(k0 + k) * ldb + (n0 + n)];
            }
        } else {
#pragma unroll
            for (int t = 0; t < (BKD * BN) / 256; t++) {
                int i = tid + t * 256;
                int n = i / BKD, k = i % BKD;
                Bs[k][n] = B[(long)(n0 + n) * ldb + (k0 + k)];
            }
        }
        __syncthreads();

#pragma unroll
        for (int k = 0; k < BKD; k++) {
            float a[TM], bb[TN];
#pragma unroll
            for (int i = 0; i < TM; i++) a[i] = As[k][ty * TM + i];
#pragma unroll
            for (int j = 0; j < TN; j++) bb[j] = Bs[k][tx * TN + j];
#pragma unroll
            for (int i = 0; i < TM; i++)
#pragma unroll
                for (int j = 0; j < TN; j++)
                    acc[i][j] = fmaf(a[i], bb[j], acc[i][j]);
        }
        __syncthreads();
    }

#pragma unroll
    for (int i = 0; i < TM; i++) {
        int m = m0 + ty * TM + i;
        float bm = biasM ? biasM[m] : 0.f;
#pragma unroll
        for (int j = 0; j < TN; j++) {
            int n = n0 + tx * TN + j;
            float bn = biasN ? biasN[n] : 0.f;
            C[(long)m * ldc + n] = alpha * acc[i][j] + bm + bn;
        }
    }
}

// ---------------- helpers ----------------

// bq_eff[f] = sum_e proj_in_b[e]*wq_w[e,f] + wq_b[f]
__global__ void fold_bias_kernel(const float* __restrict__ pib,
                                 const float* __restrict__ wq,
                                 const float* __restrict__ wqb,
                                 float* __restrict__ out)
{
    int f = blockIdx.x * blockDim.x + threadIdx.x;
    if (f >= EMB) return;
    float s = wqb[f];
    for (int e = 0; e < EMB; e++) s = fmaf(pib[e], wq[e * EMB + f], s);
    out[f] = s;
}

// row-wise softmax over [rows, 1024]; one block (256 thr) per row
__global__ void __launch_bounds__(256) softmax_rows_kernel(float* __restrict__ S)
{
    float* row = S + (long)blockIdx.x * LCTX;
    const int t = threadIdx.x;
    float v[4];
    float mx = -INFINITY;
#pragma unroll
    for (int j = 0; j < 4; j++) {
        v[j] = row[t + j * 256];
        mx = fmaxf(mx, v[j]);
    }
    __shared__ float red[256];
    red[t] = mx;
    __syncthreads();
    for (int s = 128; s > 0; s >>= 1) {
        if (t < s) red[t] = fmaxf(red[t], red[t + s]);
        __syncthreads();
    }
    mx = red[0];
    __syncthreads();
    float sum = 0.f;
#pragma unroll
    for (int j = 0; j < 4; j++) {
        v[j] = __expf(v[j] - mx);
        sum += v[j];
    }
    red[t] = sum;
    __syncthreads();
    for (int s = 128; s > 0; s >>= 1) {
        if (t < s) red[t] += red[t + s];
        __syncthreads();
    }
    float inv = 1.f / red[0];
#pragma unroll
    for (int j = 0; j < 4; j++) row[t + j * 256] = v[j] * inv;
}

// copy input [b][512][4096] into Z rows [0,512) of [b][1024][4096]
__global__ void copy_input_to_Z_kernel(const float4* __restrict__ in, float4* __restrict__ Z)
{
    long idx = (long)blockIdx.x * blockDim.x + threadIdx.x;   // over BATCH*512*4096/4
    const long per_b = (long)EMB * HW / 4;                    // 524288
    long b = idx / per_b;
    long r = idx - b * per_b;
    Z[b * ((long)2 * EMB * HW / 4) + r] = in[idx];
}

// ---------------- launch ----------------
extern "C" void kernel_launch(void* const* d_in, const int* in_sizes, int n_in,
                              void* d_out, int out_size)
{
    const float* input      = (const float*)d_in[0];   // [8,512,64,64]
    const float* context    = (const float*)d_in[1];   // [8,512,32,32]
    const float* proj_in_w  = (const float*)d_in[2];   // [512,512] (e,c)
    const float* proj_in_b  = (const float*)d_in[3];   // [512]
    const float* wq_w       = (const float*)d_in[4];   // [512,512] (in,out)
    const float* wq_b       = (const float*)d_in[5];
    const float* wk_w       = (const float*)d_in[6];
    const float* wk_b       = (const float*)d_in[7];
    const float* wv_w       = (const float*)d_in[8];
    const float* wv_b       = (const float*)d_in[9];
    const float* proj_out_w = (const float*)d_in[10];  // [512,1024]
    const float* proj_out_b = (const float*)d_in[11];  // [512]
    float* out = (float*)d_out;                        // [8,512,64,64]

    float *Wq, *bq, *Q, *Kb, *Vb, *S, *Z;
    cudaGetSymbolAddress((void**)&Wq, g_Wq);
    cudaGetSymbolAddress((void**)&bq, g_bq);
    cudaGetSymbolAddress((void**)&Q,  g_Q);
    cudaGetSymbolAddress((void**)&Kb, g_K);
    cudaGetSymbolAddress((void**)&Vb, g_V);
    cudaGetSymbolAddress((void**)&S,  g_S);
    cudaGetSymbolAddress((void**)&Z,  g_Z);

    const float scale = 1.0f / sqrtf((float)EMB);

    // 1) Wq_eff[c,f] = sum_e proj_in_w[e,c] * wq_w[e,f]   (TN, K=512)
    {
        dim3 grid(EMB / BN, EMB / BM, 1);
        sgemm_kernel<true, false><<<grid, 256>>>(
            proj_in_w, EMB, 0, wq_w, EMB, 0, Wq, EMB, 0,
            EMB, EMB, EMB, 1.0f, nullptr, nullptr);
    }
    // 2) folded bias
    fold_bias_kernel<<<2, 256>>>(proj_in_b, wq_w, wq_b, bq);

    // 3) Q[b,p,f] = sum_c input[b,c,p] * Wq_eff[c,f] + bq[f]   (TN)
    {
        dim3 grid(EMB / BN, HW / BM, BATCH);
        sgemm_kernel<true, false><<<grid, 256>>>(
            input, HW, (long)EMB * HW,
            Wq, EMB, 0,
            Q, EMB, (long)HW * EMB,
            HW, EMB, EMB, 1.0f, nullptr, bq);
    }
    // 4) K[b,l,f] = sum_c context[b,c,l] * wk_w[c,f] + wk_b[f]   (TN)
    {
        dim3 grid(EMB / BN, LCTX / BM, BATCH);
        sgemm_kernel<true, false><<<grid, 256>>>(
            context, LCTX, (long)EMB * LCTX,
            wk_w, EMB, 0,
            Kb, EMB, (long)LCTX * EMB,
            LCTX, EMB, EMB, 1.0f, nullptr, wk_b);
    }
    // 5) V[b,l,f]
    {
        dim3 grid(EMB / BN, LCTX / BM, BATCH);
        sgemm_kernel<true, false><<<grid, 256>>>(
            context, LCTX, (long)EMB * LCTX,
            wv_w, EMB, 0,
            Vb, EMB, (long)LCTX * EMB,
            LCTX, EMB, EMB, 1.0f, nullptr, wv_b);
    }
    // 6) S[b,p,l] = scale * sum_f Q[b,p,f]*K[b,l,f]   (NT)
    {
        dim3 grid(LCTX / BN, HW / BM, BATCH);
        sgemm_kernel<false, true><<<grid, 256>>>(
            Q, EMB, (long)HW * EMB,
            Kb, EMB, (long)LCTX * EMB,
            S, LCTX, (long)HW * LCTX,
            HW, LCTX, EMB, scale, nullptr, nullptr);
    }
    // 7) softmax over L
    softmax_rows_kernel<<<BATCH * HW, 256>>>(S);

    // 8) copy input into Z rows [0,512)
    {
        long n4 = (long)BATCH * EMB * HW / 4;
        copy_input_to_Z_kernel<<<(int)(n4 / 256), 256>>>((const float4*)input, (float4*)Z);
    }
    // 9) Z[b, 512+e, p] = O^T[e,p] = sum_l V[b,l,e] * P[b,p,l]   (TT: A=V [K=L,M=E], B=S [N=P,K=L])
    {
        dim3 grid(HW / BN, EMB / BM, BATCH);
        sgemm_kernel<true, true><<<grid, 256>>>(
            Vb, EMB, (long)LCTX * EMB,
            S, LCTX, (long)HW * LCTX,
            Z + (long)EMB * HW, HW, (long)2 * EMB * HW,
            EMB, HW, LCTX, 1.0f, nullptr, nullptr);
    }
    // 10) out[b,o,p] = sum_k proj_out_w[o,k] * Z[b,k,p] + proj_out_b[o]   (NN)
    {
        dim3 grid(HW / BN, EMB / BM, BATCH);
        sgemm_kernel<false, false><<<grid, 256>>>(
            proj_out_w, 2 * EMB, 0,
            Z, HW, (long)2 * EMB * HW,
            out, HW, (long)EMB * HW,
            EMB, HW, 2 * EMB, 1.0f, proj_out_b, nullptr);
    }
}